// round 7
// baseline (speedup 1.0000x reference)
#include <cuda_runtime.h>
#include <cstdint>

#define N_DENSE    64
#define N_SAMPLES  121
#define N_CHANNELS 384
#define BATCH      2048
#define ROW_IN     (N_DENSE * (1 + N_SAMPLES))   // 7808 floats per input row
#define ROW_OUT    (N_CHANNELS * N_SAMPLES)      // 46464 floats per output batch
#define N_VEC      (ROW_OUT / 4)                 // 11616 float4 per batch row
#define NTHREADS   256                           // 8 warps -> 8 CTAs/SM (64/64 warps)

// One CTA per batch element. NO smem staging: chain data is read directly
// (L2-resident across replays, ~240cyc, fully coalesced). Tiny smem footprint
// -> full occupancy; stores start immediately. Flat vec4 output mapping with
// incremental (c,s); straddle vec4s via two predicated chain walks.
__global__ __launch_bounds__(NTHREADS)
void sparse_input_gather_v7(const float* __restrict__ in,
                            float* __restrict__ out)
{
    __shared__ int head[N_CHANNELS];
    __shared__ int nxt[N_DENSE];

    const int b = blockIdx.x;
    const int t = threadIdx.x;

    const float* __restrict__ row  = in + (size_t)b * ROW_IN;
    const float* __restrict__ data = row + N_DENSE;

    // ---- build inverted index (only work before the store stream) ----
    int my_c = -1;
    if (t < N_DENSE) {
        int c = (int)__ldg(&row[t]);
        my_c = max(0, min(N_CHANNELS - 1, c));
    }
    #pragma unroll
    for (int i = t; i < N_CHANNELS; i += NTHREADS) head[i] = -1;
    __syncthreads();
    if (t < N_DENSE)
        nxt[t] = atomicExch(&head[my_c], t);
    __syncthreads();

    // ---- gather ----
    float4* __restrict__ ovec = reinterpret_cast<float4*>(out + (size_t)b * ROW_OUT);

    // (c, s) for p = 4t; stride NTHREADS vec4 = 1024 floats = 8*121 + 56
    int c = (4 * t) / N_SAMPLES;
    int s = 4 * t - c * N_SAMPLES;

    #pragma unroll 4
    for (int v = t; v < N_VEC; v += NTHREADS) {
        float4 acc = make_float4(0.f, 0.f, 0.f, 0.f);

        if (s <= N_SAMPLES - 4) {
            // fast path: all 4 samples in channel c (~85% of chains empty -> skip)
            int d = head[c];
            while (d >= 0) {
                const float* g = data + d * N_SAMPLES + s;   // coalesced across lanes
                acc.x += __ldg(g + 0);
                acc.y += __ldg(g + 1);
                acc.z += __ldg(g + 2);
                acc.w += __ldg(g + 3);
                d = nxt[d];
            }
        } else {
            // straddle: nA = 121 - s in {1,2,3} samples from c, rest from c+1
            const int nA = N_SAMPLES - s;
            int d = head[c];
            while (d >= 0) {                                 // walk A: channel c
                const float* g = data + d * N_SAMPLES + s;
                acc.x += __ldg(g + 0);
                if (nA > 1) acc.y += __ldg(g + 1);
                if (nA > 2) acc.z += __ldg(g + 2);
                d = nxt[d];
            }
            int d2 = head[c + 1];
            while (d2 >= 0) {                                // walk B: channel c+1
                const float* g2 = data + d2 * N_SAMPLES - nA; // + j, j in [nA,3]
                if (nA < 2) acc.y += __ldg(g2 + 1);
                if (nA < 3) acc.z += __ldg(g2 + 2);
                acc.w += __ldg(g2 + 3);
                d2 = nxt[d2];
            }
        }
        __stcs(&ovec[v], acc);          // streaming 128-bit store

        // advance (c, s) by 1024 flat elements: c += 8, s += 56, wrap
        s += 56; c += 8;
        if (s >= N_SAMPLES) { s -= N_SAMPLES; c++; }
    }
}

extern "C" void kernel_launch(void* const* d_in, const int* in_sizes, int n_in,
                              void* d_out, int out_size)
{
    const float* in  = (const float*)d_in[0];
    float*       out = (float*)d_out;
    sparse_input_gather_v7<<<BATCH, NTHREADS>>>(in, out);
}

// round 8
// speedup vs baseline: 1.1274x; 1.1274x over previous
#include <cuda_runtime.h>
#include <cstdint>

#define N_DENSE    64
#define N_SAMPLES  121
#define N_CHANNELS 384
#define BATCH      2048
#define ROW_IN     (N_DENSE * (1 + N_SAMPLES))   // 7808 floats per input row
#define ROW_OUT    (N_CHANNELS * N_SAMPLES)      // 46464 floats per output batch
#define N_VEC      (ROW_OUT / 4)                 // 11616 float4 per batch row
#define DATA_F     (N_DENSE * N_SAMPLES)         // 7744 floats of sample data
#define NTHREADS   384
#define HEAD_PAD   400                           // head[] padded for 1-ahead prefetch

__device__ __forceinline__ void cp16(float* dst_smem, const float4* src) {
    uint32_t d = (uint32_t)__cvta_generic_to_shared(dst_smem);
    asm volatile("cp.async.cg.shared.global [%0], [%1], 16;\n" :: "r"(d), "l"(src));
}

// v6 structure (one CTA per batch row, smem-staged data, incremental (c,s),
// two-walk straddle, streaming vec4 stores) with the chain-head LDS moved off
// the critical path: head[c]/head[c+1] for iteration i+1 are prefetched into
// registers during iteration i, so the per-iteration branch tests a register
// instead of a 29-cyc LDS result. Phase-1 copy via cp.async (no reg round-trip).
__global__ __launch_bounds__(NTHREADS)
void sparse_input_gather_v8(const float* __restrict__ in,
                            float* __restrict__ out)
{
    __shared__ float sdata[DATA_F + 4];   // staged [64][121]
    __shared__ int   head[HEAD_PAD];      // chain heads, padded with -1
    __shared__ int   nxt[N_DENSE];

    const int b = blockIdx.x;
    const int t = threadIdx.x;

    const float* __restrict__ row  = in + (size_t)b * ROW_IN;
    const float* __restrict__ data = row + N_DENSE;

    // ---- phase 1: async-stage data, build inverted index ----
    int my_c = -1;
    if (t < N_DENSE) {
        int c = (int)__ldg(&row[t]);
        my_c = max(0, min(N_CHANNELS - 1, c));
    }
    #pragma unroll
    for (int i = t; i < HEAD_PAD; i += NTHREADS) head[i] = -1;

    {
        const float4* __restrict__ src = reinterpret_cast<const float4*>(data);
        #pragma unroll
        for (int i = t; i < DATA_F / 4; i += NTHREADS)   // 1936 vec4, fire-and-forget
            cp16(&sdata[4 * i], &src[i]);
        asm volatile("cp.async.commit_group;\n" ::: "memory");
    }
    __syncthreads();                       // head[] init visible
    if (t < N_DENSE)
        nxt[t] = atomicExch(&head[my_c], t);
    asm volatile("cp.async.wait_group 0;\n" ::: "memory");
    __syncthreads();                       // sdata + chains visible

    // ---- phase 2: gather with 1-ahead head prefetch ----
    float4* __restrict__ ovec = reinterpret_cast<float4*>(out + (size_t)b * ROW_OUT);

    // (c, s) for p = 4t; stride NTHREADS vec4 = 1536 floats = 12*121 + 84
    int c = (4 * t) / N_SAMPLES;
    int s = 4 * t - c * N_SAMPLES;

    int hA = head[c];
    int hB = head[c + 1];

    #pragma unroll 2
    for (int v = t; v < N_VEC; v += NTHREADS) {
        // prefetch next iteration's heads (off critical path)
        int c2 = c + 12, s2 = s + 84;
        if (s2 >= N_SAMPLES) { s2 -= N_SAMPLES; c2++; }
        const int hA2 = head[c2];
        const int hB2 = head[c2 + 1];

        float4 acc = make_float4(0.f, 0.f, 0.f, 0.f);

        if (s <= N_SAMPLES - 4) {
            // fast path: all 4 samples in channel c
            int d = hA;
            while (d >= 0) {
                const float* g = sdata + d * N_SAMPLES + s;
                acc.x += g[0];
                acc.y += g[1];
                acc.z += g[2];
                acc.w += g[3];
                d = nxt[d];
            }
        } else {
            // straddle: nA = 121 - s in {1,2,3} from channel c, rest from c+1
            const int nA = N_SAMPLES - s;
            int d = hA;
            while (d >= 0) {
                const float* g = sdata + d * N_SAMPLES + s;
                acc.x += g[0];
                if (nA > 1) acc.y += g[1];
                if (nA > 2) acc.z += g[2];
                d = nxt[d];
            }
            int d2 = hB;
            while (d2 >= 0) {
                const float* g2 = sdata + d2 * N_SAMPLES - nA;   // + j, j in [nA,3]
                if (nA < 2) acc.y += g2[1];
                if (nA < 3) acc.z += g2[2];
                acc.w += g2[3];
                d2 = nxt[d2];
            }
        }
        __stcs(&ovec[v], acc);             // streaming 128-bit store

        c = c2; s = s2; hA = hA2; hB = hB2;
    }
}

extern "C" void kernel_launch(void* const* d_in, const int* in_sizes, int n_in,
                              void* d_out, int out_size)
{
    const float* in  = (const float*)d_in[0];
    float*       out = (float*)d_out;
    sparse_input_gather_v8<<<BATCH, NTHREADS>>>(in, out);
}